// round 5
// baseline (speedup 1.0000x reference)
#include <cuda_runtime.h>
#include <cuda_bf16.h>

#define NVOX 500000
#define CIN1 32
#define COUT 64
#define KK 27
#define NB_STATS 512

typedef unsigned long long u64;

// ---------------- scratch (allocation-free: __device__ globals) ----------------
__device__ __align__(16) float g_h1[(NVOX + 1) * CIN1];  // bn1+relu(x), row NVOX = 0
__device__ __align__(16) float g_h2[(NVOX + 1) * COUT];  // conv1 out -> bn2+relu in place
__device__ __align__(16) float g_part[NB_STATS * COUT * 2];
__device__ __align__(16) float g_ab1[2 * CIN1];  // [A | B] scale/shift stage 1
__device__ __align__(16) float g_ab2[2 * COUT];  // [A | B] scale/shift stage 2

// ---------------- f32x2 packed-math helpers ----------------
__device__ __forceinline__ u64 pack2(float x, float y) {
    u64 r; asm("mov.b64 %0, {%1, %2};" : "=l"(r) : "f"(x), "f"(y)); return r;
}
__device__ __forceinline__ void unpack2(u64 v, float& x, float& y) {
    asm("mov.b64 {%0, %1}, %2;" : "=f"(x), "=f"(y) : "l"(v));
}
__device__ __forceinline__ void ffma2(u64& d, u64 a, u64 b) {
    asm("fma.rn.f32x2 %0, %1, %2, %3;" : "=l"(d) : "l"(a), "l"(b), "l"(d));
}

// ---------------- BN stats: deterministic two-level reduction ----------------
template <int C>
__global__ void bn_stats_kernel(const float* __restrict__ in_param, int n) {
    const float* __restrict__ in = in_param ? in_param : g_h2;
    constexpr int RL = 256 / C;
    int tid = threadIdx.x;
    int c = tid % C;
    int rl = tid / C;
    float s = 0.f, q = 0.f;
    for (long long r = (long long)blockIdx.x * RL + rl; r < n;
         r += (long long)gridDim.x * RL) {
        float v = in[r * C + c];
        s += v; q += v * v;
    }
    __shared__ __align__(16) float ss[256];
    __shared__ __align__(16) float sq[256];
    ss[tid] = s; sq[tid] = q;
    __syncthreads();
    for (int step = 128; step >= C; step >>= 1) {
        if (tid < step) { ss[tid] += ss[tid + step]; sq[tid] += sq[tid + step]; }
        __syncthreads();
    }
    if (tid < C) {
        g_part[blockIdx.x * 2 * C + c] = ss[tid];
        g_part[blockIdx.x * 2 * C + C + c] = sq[tid];
    }
}

template <int C>
__global__ void bn_final_kernel(const float* __restrict__ g,
                                const float* __restrict__ b, float invn) {
    int c = threadIdx.x;
    if (c >= C) return;
    float* ab = (C == CIN1) ? g_ab1 : g_ab2;
    float s = 0.f, q = 0.f;
#pragma unroll 4
    for (int i = 0; i < NB_STATS; i++) {
        s += g_part[i * 2 * C + c];
        q += g_part[i * 2 * C + C + c];
    }
    float m = s * invn;
    float v = q * invn - m * m;
    float A = g[c] * rsqrtf(v + 1e-5f);
    ab[c] = A;
    ab[C + c] = b[c] - m * A;
}

// ---------------- normalize + ReLU (+ zero sentinel row) ----------------
template <int STAGE>
__global__ void bn_apply_kernel(const float* __restrict__ src_param, long long nvec) {
    constexpr int C = (STAGE == 1) ? CIN1 : COUT;
    const float* __restrict__ ab = (STAGE == 1) ? g_ab1 : g_ab2;
    const float4* __restrict__ src =
        (STAGE == 1) ? (const float4*)src_param : (const float4*)g_h2;
    float4* __restrict__ dst = (STAGE == 1) ? (float4*)g_h1 : (float4*)g_h2;

    long long stride = (long long)gridDim.x * blockDim.x;
    for (long long i = (long long)blockIdx.x * blockDim.x + threadIdx.x; i < nvec;
         i += stride) {
        float4 v = src[i];
        int c0 = (int)((i * 4) % C);
        float4 o;
        o.x = fmaxf(fmaf(v.x, ab[c0 + 0], ab[C + c0 + 0]), 0.f);
        o.y = fmaxf(fmaf(v.y, ab[c0 + 1], ab[C + c0 + 1]), 0.f);
        o.z = fmaxf(fmaf(v.z, ab[c0 + 2], ab[C + c0 + 2]), 0.f);
        o.w = fmaxf(fmaf(v.w, ab[c0 + 3], ab[C + c0 + 3]), 0.f);
        dst[i] = o;
    }
    // zero the sentinel row (index NVOX)
    long long t = (long long)blockIdx.x * blockDim.x + threadIdx.x;
    if (t < C) {
        float* d = (STAGE == 1) ? g_h1 : g_h2;
        d[(long long)NVOX * C + t] = 0.f;
    }
}

// ---------------- gather-GEMM sparse conv ----------------
// Block tile: 128 voxels x 64 out channels, 256 threads.
// A staged in shared in 32-channel slabs (transposed). Thread: 4 vox x 8 ch,
// all FMAs as packed f32x2.
template <int CIN, bool RES>
__global__ void __launch_bounds__(256)
conv_kernel(const int* __restrict__ nbr, const float* __restrict__ W,
            const float* __restrict__ xres, const float* __restrict__ Wres,
            const float* __restrict__ bres, float* __restrict__ out_param, int n) {
    constexpr int VT = 128;
    constexpr int NCH = CIN / 32;  // 32-channel slabs
    __shared__ __align__(16) float Ws[CIN * 64];  // full W[k]
    __shared__ __align__(16) float As[32 * VT];   // one slab, transposed [cl][v]
    __shared__ __align__(16) int Is[VT * KK];

    const float* __restrict__ feat = (CIN == CIN1) ? g_h1 : g_h2;
    float* __restrict__ out = RES ? out_param : g_h2;

    int tid = threadIdx.x;
    long long base = (long long)blockIdx.x * VT;

    for (int i = tid; i < VT * KK; i += 256) {
        long long gv = base + (i / KK);
        Is[i] = (gv < n) ? nbr[gv * KK + (i % KK)] : n;
    }

    u64 acc[4][4];
#pragma unroll
    for (int a = 0; a < 4; a++)
#pragma unroll
        for (int b = 0; b < 4; b++) acc[a][b] = 0ull;

    const int vg = tid >> 3;      // voxel group: voxels vg*4 .. vg*4+3
    const int cg = tid & 7;       // channel-pair lane: pairs at 2*cg + 16*p
    const int v = tid >> 1;       // gather: voxel per thread-pair
    const int part = tid & 1;     // gather: half of 32-ch slab

    for (int k = 0; k < KK; ++k) {
        __syncthreads();  // previous compute done -> safe to overwrite Ws/As
        // W[k] -> Ws (row-major [CIN][64])
        {
            const float4* wsrc =
                reinterpret_cast<const float4*>(W + (long long)k * CIN * 64);
            float4* wdst = reinterpret_cast<float4*>(Ws);
            for (int i = tid; i < CIN * 16; i += 256) wdst[i] = wsrc[i];
        }
#pragma unroll
        for (int ch = 0; ch < NCH; ++ch) {
            if (ch > 0) __syncthreads();  // prior slab compute done
            // gather slab ch transposed: As[cl][v], cl = channel-in-slab
            {
                const long long idx = Is[v * KK + k];
                const float4* src =
                    reinterpret_cast<const float4*>(feat + idx * CIN + ch * 32);
#pragma unroll
                for (int j = 0; j < 4; ++j) {
                    int f4i = part * 4 + j;
                    float4 t = src[f4i];
                    As[(f4i * 4 + 0) * VT + v] = t.x;
                    As[(f4i * 4 + 1) * VT + v] = t.y;
                    As[(f4i * 4 + 2) * VT + v] = t.z;
                    As[(f4i * 4 + 3) * VT + v] = t.w;
                }
            }
            __syncthreads();
#pragma unroll 8
            for (int cl = 0; cl < 32; ++cl) {
                float4 av =
                    *reinterpret_cast<const float4*>(&As[cl * VT + (vg << 2)]);
                const u64* wr =
                    reinterpret_cast<const u64*>(Ws + (ch * 32 + cl) * 64);
                u64 w0 = wr[cg], w1 = wr[cg + 8], w2 = wr[cg + 16], w3 = wr[cg + 24];
                u64 a0 = pack2(av.x, av.x), a1 = pack2(av.y, av.y);
                u64 a2 = pack2(av.z, av.z), a3 = pack2(av.w, av.w);
                ffma2(acc[0][0], a0, w0); ffma2(acc[0][1], a0, w1);
                ffma2(acc[0][2], a0, w2); ffma2(acc[0][3], a0, w3);
                ffma2(acc[1][0], a1, w0); ffma2(acc[1][1], a1, w1);
                ffma2(acc[1][2], a1, w2); ffma2(acc[1][3], a1, w3);
                ffma2(acc[2][0], a2, w0); ffma2(acc[2][1], a2, w1);
                ffma2(acc[2][2], a2, w2); ffma2(acc[2][3], a2, w3);
                ffma2(acc[3][0], a3, w0); ffma2(acc[3][1], a3, w1);
                ffma2(acc[3][2], a3, w2); ffma2(acc[3][3], a3, w3);
            }
        }
    }

    if (RES) {
        // residual: acc += x[v] @ Wres  (32 -> 64), one slab
        __syncthreads();
        {
            const float4* wsrc = reinterpret_cast<const float4*>(Wres);
            float4* wdst = reinterpret_cast<float4*>(Ws);
            for (int i = tid; i < 32 * 16; i += 256) wdst[i] = wsrc[i];
        }
        {
            long long gv = base + v;
            if (gv < n) {
                const float4* src = reinterpret_cast<const float4*>(xres + gv * 32);
#pragma unroll
                for (int j = 0; j < 4; ++j) {
                    int f4i = part * 4 + j;
                    float4 t = src[f4i];
                    As[(f4i * 4 + 0) * VT + v] = t.x;
                    As[(f4i * 4 + 1) * VT + v] = t.y;
                    As[(f4i * 4 + 2) * VT + v] = t.z;
                    As[(f4i * 4 + 3) * VT + v] = t.w;
                }
            }
        }
        __syncthreads();
#pragma unroll 8
        for (int cl = 0; cl < 32; ++cl) {
            float4 av = *reinterpret_cast<const float4*>(&As[cl * VT + (vg << 2)]);
            const u64* wr = reinterpret_cast<const u64*>(Ws + cl * 64);
            u64 w0 = wr[cg], w1 = wr[cg + 8], w2 = wr[cg + 16], w3 = wr[cg + 24];
            u64 a0 = pack2(av.x, av.x), a1 = pack2(av.y, av.y);
            u64 a2 = pack2(av.z, av.z), a3 = pack2(av.w, av.w);
            ffma2(acc[0][0], a0, w0); ffma2(acc[0][1], a0, w1);
            ffma2(acc[0][2], a0, w2); ffma2(acc[0][3], a0, w3);
            ffma2(acc[1][0], a1, w0); ffma2(acc[1][1], a1, w1);
            ffma2(acc[1][2], a1, w2); ffma2(acc[1][3], a1, w3);
            ffma2(acc[2][0], a2, w0); ffma2(acc[2][1], a2, w1);
            ffma2(acc[2][2], a2, w2); ffma2(acc[2][3], a2, w3);
            ffma2(acc[3][0], a3, w0); ffma2(acc[3][1], a3, w1);
            ffma2(acc[3][2], a3, w2); ffma2(acc[3][3], a3, w3);
        }
    }

#pragma unroll
    for (int vv = 0; vv < 4; ++vv) {
        long long gv = base + (vg * 4 + vv);
        if (gv >= n) continue;
        float* o = out + gv * 64;
#pragma unroll
        for (int p = 0; p < 4; ++p) {
            float lo, hi;
            unpack2(acc[vv][p], lo, hi);
            int c0 = 2 * cg + 16 * p;
            if (RES) { lo += bres[c0]; hi += bres[c0 + 1]; }
            *reinterpret_cast<float2*>(o + c0) = make_float2(lo, hi);
        }
    }
}

// ---------------- launch ----------------
extern "C" void kernel_launch(void* const* d_in, const int* in_sizes, int n_in,
                              void* d_out, int out_size) {
    const float* x = (const float*)d_in[0];
    const int* nbr = (const int*)d_in[1];  // JAX default x64-disabled -> int32
    const float* W1 = (const float*)d_in[2];
    const float* W2 = (const float*)d_in[3];
    const float* Wres = (const float*)d_in[4];
    const float* bres = (const float*)d_in[5];
    const float* g1 = (const float*)d_in[6];
    const float* b1 = (const float*)d_in[7];
    const float* g2 = (const float*)d_in[8];
    const float* b2 = (const float*)d_in[9];
    float* out = (float*)d_out;

    const int n = NVOX;
    const float invn = 1.0f / (float)n;
    const int conv_grid = (n + 127) / 128;  // 3907

    // Stage 1: bn1 + relu
    bn_stats_kernel<CIN1><<<NB_STATS, 256>>>(x, n);
    bn_final_kernel<CIN1><<<1, 32>>>(g1, b1, invn);
    bn_apply_kernel<1><<<2048, 256>>>(x, (long long)n * CIN1 / 4);
    // conv1: g_h1 -> g_h2
    conv_kernel<CIN1, false><<<conv_grid, 256>>>(nbr, W1, nullptr, nullptr, nullptr,
                                                 nullptr, n);
    // Stage 2: bn2 + relu (in place on g_h2)
    bn_stats_kernel<COUT><<<NB_STATS, 256>>>(nullptr, n);
    bn_final_kernel<COUT><<<1, 64>>>(g2, b2, invn);
    bn_apply_kernel<2><<<2048, 256>>>(nullptr, (long long)n * COUT / 4);
    // conv2 + residual -> out
    conv_kernel<COUT, true><<<conv_grid, 256>>>(nbr, W2, x, Wres, bres, out, n);
}